// round 17
// baseline (speedup 1.0000x reference)
#include <cuda_runtime.h>
#include <cstdint>

// Degenerate conv (reference uses only x[:,0] and w[:,2]):
//   out(n,f,i,j) = bias[f] + sum_{a,b} w[f,2,a,b] * x[n,0,i+a,j+b]
//   x: (16,3,256,256) f32, w: (64,3,3,3) f32, b: (64,) f32
//   out: (16,64,254,254) f32
//
// At the pure-write HBM asymptote: 264MB fp32 output, evict-first (.cs)
// stores drain at ~5.4TB/s => ~48us. Geometry (== R16 champion):
//   main blocks (bx < 127): 1 row x 4 cols per thread (t=0..62), 16 filters,
//   all stores 16B-aligned warp-dense STG.128.cs; even rows j=4t, odd rows
//   j=4t+2 (row stride 1016B == 8 mod 16). Strip block (bx==127): for
//   row-pair ip, out[2ip][252..253] + out[2ip+1][0..1] contiguous 16B ->
//   one STG.128.cs per filter. Weights in __constant__ (uniform LDC port,
//   one CE node); bias via uniform LDG.128 + static selects.
// This round: split FFMA2 chains (2 partials per accumulator) + __ldg input.
#define NB     16
#define F_OUT  64
#define F_Q    16
#define Hh     256
#define Ww     256
#define HO     254
#define WO     254
#define OIMG   (HO * WO)          // 64516

typedef unsigned long long u64;

__constant__ float c_w[F_OUT * 27];   // full weight tensor (we use [f][2][*])

// packed f32x2 FMA (Blackwell): d = a * w + c on both lanes
static __device__ __forceinline__ u64 ffma2(u64 a, u64 w, u64 c) {
    u64 d;
    asm("fma.rn.f32x2 %0, %1, %2, %3;" : "=l"(d) : "l"(a), "l"(w), "l"(c));
    return d;
}

// packed f32x2 add
static __device__ __forceinline__ u64 fadd2(u64 a, u64 b) {
    u64 d;
    asm("add.rn.f32x2 %0, %1, %2;" : "=l"(d) : "l"(a), "l"(b));
    return d;
}

static __device__ __forceinline__ u64 pack2(float lo, float hi) {
    u64 d;
    asm("mov.b64 %0, {%1, %2};" : "=l"(d) : "f"(lo), "f"(hi));
    return d;
}

// evict-first 16B store: output is a write-once stream
static __device__ __forceinline__ void stcs128(float* p, u64 a, u64 b) {
    asm volatile("st.global.cs.v2.b64 [%0], {%1, %2};"
                 :: "l"(p), "l"(a), "l"(b) : "memory");
}

// Per-filter 9-FMA with split chains:
//   even-k terms accumulate into acc (seeded with bias),
//   odd-k terms into a second partial, summed at the end.
static __device__ __forceinline__ u64 conv9(const u64 Prow[3][5], int col,
                                            const float* wf, u64 bias2) {
    u64 s0 = bias2, s1 = 0;
    // unrolled 3x3, alternating partials
    {
        const float w0 = wf[0]; s0 = ffma2(Prow[0][col],     pack2(w0, w0), s0);
        const float w1 = wf[1]; s1 = ffma2(Prow[0][col + 1], pack2(w1, w1), pack2(0.f, 0.f));
        const float w2 = wf[2]; s0 = ffma2(Prow[0][col + 2], pack2(w2, w2), s0);
        const float w3 = wf[3]; s1 = ffma2(Prow[1][col],     pack2(w3, w3), s1);
        const float w4 = wf[4]; s0 = ffma2(Prow[1][col + 1], pack2(w4, w4), s0);
        const float w5 = wf[5]; s1 = ffma2(Prow[1][col + 2], pack2(w5, w5), s1);
        const float w6 = wf[6]; s0 = ffma2(Prow[2][col],     pack2(w6, w6), s0);
        const float w7 = wf[7]; s1 = ffma2(Prow[2][col + 1], pack2(w7, w7), s1);
        const float w8 = wf[8]; s0 = ffma2(Prow[2][col + 2], pack2(w8, w8), s0);
    }
    return fadd2(s0, s1);
}

__global__ __launch_bounds__(128) void conv2dcq_kernel(
    const float* __restrict__ x,
    const float* __restrict__ bias,
    float* __restrict__ out) {

    const int tid = threadIdx.x;
    const int n   = blockIdx.y;
    const int f0  = blockIdx.z * F_Q;     // block-uniform filter base

    const float* xim = x + (size_t)n * 3 * Hh * Ww;        // channel 0
    float* oimg = out + (size_t)n * F_OUT * OIMG + (size_t)f0 * OIMG;

    // bias for this quarter: 4 uniform LDG.128 (64B-aligned)
    const float4* b4 = reinterpret_cast<const float4*>(bias + f0);

    if (blockIdx.x < 127) {
        // ================= main: STG.128.cs tiles, t = 0..62 ===============
        const int rs = tid >> 6;              // row parity, warp-uniform
        const int t  = tid & 63;              // col tile 0..63
        if (t >= 63) return;                  // coverage guard

        const int i  = blockIdx.x * 2 + rs;   // output row
        const int j  = 4 * t + 2 * rs;        // 16B-aligned store col

        const float* xrow = xim + (size_t)i * Ww;

        // P[r][s] = (x[i+r][j+s], x[i+r][j+s+1]), r=0..2, s=0..4
        u64 P[3][5];
        if (rs == 0) {                        // warp-uniform branch
            #pragma unroll
            for (int r = 0; r < 3; r++) {
                const float* xr = xrow + (size_t)r * Ww + j;
                const float4 a = __ldg(reinterpret_cast<const float4*>(xr));
                const float2 b = __ldg(reinterpret_cast<const float2*>(xr + 4));
                P[r][0] = pack2(a.x, a.y);
                P[r][1] = pack2(a.y, a.z);
                P[r][2] = pack2(a.z, a.w);
                P[r][3] = pack2(a.w, b.x);
                P[r][4] = pack2(b.x, b.y);
            }
        } else {
            #pragma unroll
            for (int r = 0; r < 3; r++) {
                const float* xr = xrow + (size_t)r * Ww + j;
                const float2 a = __ldg(reinterpret_cast<const float2*>(xr));
                const float4 b = __ldg(reinterpret_cast<const float4*>(xr + 2));
                P[r][0] = pack2(a.x, a.y);
                P[r][1] = pack2(a.y, b.x);
                P[r][2] = pack2(b.x, b.y);
                P[r][3] = pack2(b.y, b.z);
                P[r][4] = pack2(b.z, b.w);
            }
        }

        float* ob = oimg + (size_t)i * WO + j;

        #pragma unroll
        for (int g = 0; g < 4; g++) {
            const float4 bq = __ldg(b4 + g);              // uniform LDG.128
            const float bsel[4] = {bq.x, bq.y, bq.z, bq.w};

            #pragma unroll
            for (int u = 0; u < 4; u++) {                 // static select only
                const int f = f0 + g * 4 + u;
                const float* wf = c_w + f * 27 + 18;      // uniform LDC
                const u64 bias2 = pack2(bsel[u], bsel[u]);

                const u64 a0 = conv9(P, 0, wf, bias2);    // cols j, j+1
                const u64 a1 = conv9(P, 2, wf, bias2);    // cols j+2, j+3

                // (1016*i + 4*j) % 16 == 0 by construction
                stcs128(ob, a0, a1);
                ob += (size_t)OIMG;
            }
        }
    } else {
        // ================= strip: ragged edges, one STG.128.cs/filter ======
        const int ip = tid;
        if (ip >= 127) return;
        const int i = ip * 2;

        u64 PR[3][5], PL[3][5];               // cols 0..2 used (pad for conv9)
        #pragma unroll
        for (int r = 0; r < 3; r++) {
            const float4 a = __ldg(reinterpret_cast<const float4*>(
                xim + (size_t)(i + r) * Ww + 252));
            PR[r][0] = pack2(a.x, a.y);
            PR[r][1] = pack2(a.y, a.z);
            PR[r][2] = pack2(a.z, a.w);
            PR[r][3] = PR[r][4] = 0;
            const float4 c = __ldg(reinterpret_cast<const float4*>(
                xim + (size_t)(i + 1 + r) * Ww));
            PL[r][0] = pack2(c.x, c.y);
            PL[r][1] = pack2(c.y, c.z);
            PL[r][2] = pack2(c.z, c.w);
            PL[r][3] = PL[r][4] = 0;
        }

        // out[i][252..253] + out[i+1][0..1]: contiguous, 16B-aligned (i even)
        float* ob = oimg + (size_t)i * WO + 252;

        #pragma unroll
        for (int g = 0; g < 4; g++) {
            const float4 bq = __ldg(b4 + g);
            const float bsel[4] = {bq.x, bq.y, bq.z, bq.w};

            #pragma unroll
            for (int u = 0; u < 4; u++) {
                const int f = f0 + g * 4 + u;
                const float* wf = c_w + f * 27 + 18;
                const u64 bias2 = pack2(bsel[u], bsel[u]);

                const u64 aR = conv9(PR, 0, wf, bias2);   // out[i][252..253]
                const u64 aL = conv9(PL, 0, wf, bias2);   // out[i+1][0..1]

                stcs128(ob, aR, aL);
                ob += (size_t)OIMG;
            }
        }
    }
}

extern "C" void kernel_launch(void* const* d_in, const int* in_sizes, int n_in,
                              void* d_out, int out_size) {
    const float* x    = (const float*)d_in[0];
    const float* w    = (const float*)d_in[1];
    const float* bias = (const float*)d_in[2];
    float* out        = (float*)d_out;

    // Single CE node: stage weights into constant memory (D2D, capturable).
    cudaMemcpyToSymbolAsync(c_w, w, F_OUT * 27 * sizeof(float), 0,
                            cudaMemcpyDeviceToDevice, 0);

    dim3 grid(128, NB, F_OUT / F_Q);   // (127 main + 1 strip, 16, 4)
    conv2dcq_kernel<<<grid, 128>>>(x, bias, out);
}